// round 2
// baseline (speedup 1.0000x reference)
#include <cuda_runtime.h>

#define N_ROWS 8000
#define D 9
#define N4 2000           // N_ROWS / 4
#define OUT_TPB 256
#define ROWS_PER_BLK 16
#define SCAN_TPB 1024
#define SCAN_RPT 8        // 1000 active threads * 8 rows = 8000

// Scratch (device globals — no allocation allowed)
__device__ float d_g[N_ROWS];
__device__ float d_h[N_ROWS];
__device__ float d_w1bar[N_ROWS];

// ---------------------------------------------------------------------------
// Fused kernel 1: per-row stats + cumulative scan + normalized weight.
// Single block, 1024 threads; threads 0..999 each own rows [t*8, t*8+8).
// Each thread's x-slice is 72 contiguous floats starting at t*72 (16B aligned)
// -> 18 float4 loads, consumed in order (full unroll keeps live set small).
//
//   s1[r] = sum_d ((x-c1)/a1)^2      (log-domain row membership)
//   S1[r] = cumsum(s1)               (log-domain cumprod)
//   w1bar[r] = 1/(1+exp(S1-S2))      (stable softmax over 2 rules)
//   g[r] = f1[r]-f2[r],  h[r] = f2[r]
// ---------------------------------------------------------------------------
__global__ void __launch_bounds__(SCAN_TPB, 1)
k_prologue(const float* __restrict__ x,
           const float* __restrict__ a1, const float* __restrict__ c1,
           const float* __restrict__ a2, const float* __restrict__ c2,
           const float* __restrict__ wf1, const float* __restrict__ bf1,
           const float* __restrict__ wf2, const float* __restrict__ bf2)
{
    __shared__ float sh1[SCAN_TPB];
    __shared__ float sh2[SCAN_TPB];
    const int t = threadIdx.x;
    const bool active = (t * SCAN_RPT) < N_ROWS;   // threads 0..999

    const float C1 = c1[0], C2 = c2[0];
    const float inv1 = 1.0f / a1[0];
    const float inv2 = 1.0f / a2[0];
    const float B1 = bf1[0], B2 = bf2[0];
    float W1[D], W2[D];
#pragma unroll
    for (int d = 0; d < D; d++) { W1[d] = wf1[d]; W2[d] = wf2[d]; }

    float v1[SCAN_RPT], v2[SCAN_RPT];   // per-row local cumsums
    float gg[SCAN_RPT], hh[SCAN_RPT];
    float acc1 = 0.0f, acc2 = 0.0f;

    if (active) {
        const float4* px = reinterpret_cast<const float4*>(x) + t * 18;
        float s1 = 0.f, s2 = 0.f, f1 = B1, f2 = B2;
#pragma unroll
        for (int q = 0; q < 18; q++) {
            float4 v = px[q];
            float el[4] = {v.x, v.y, v.z, v.w};
#pragma unroll
            for (int u = 0; u < 4; u++) {
                const int e = q * 4 + u;      // 0..71, all static after unroll
                const int r = e / D;
                const int d = e % D;
                if (d == 0) { s1 = 0.f; s2 = 0.f; f1 = B1; f2 = B2; }
                float xv = el[u];
                float u1 = (xv - C1) * inv1;
                float u2 = (xv - C2) * inv2;
                s1 = fmaf(u1, u1, s1);
                s2 = fmaf(u2, u2, s2);
                f1 = fmaf(xv, W1[d], f1);
                f2 = fmaf(xv, W2[d], f2);
                if (d == D - 1) {
                    acc1 += s1; v1[r] = acc1;
                    acc2 += s2; v2[r] = acc2;
                    gg[r] = f1 - f2;
                    hh[r] = f2;
                }
            }
        }
        // write g,h (float4-aligned: t*8 rows)
        float4* pg = reinterpret_cast<float4*>(d_g) + t * 2;
        float4* ph = reinterpret_cast<float4*>(d_h) + t * 2;
        pg[0] = make_float4(gg[0], gg[1], gg[2], gg[3]);
        pg[1] = make_float4(gg[4], gg[5], gg[6], gg[7]);
        ph[0] = make_float4(hh[0], hh[1], hh[2], hh[3]);
        ph[1] = make_float4(hh[4], hh[5], hh[6], hh[7]);
    }
    sh1[t] = acc1;
    sh2[t] = acc2;
    __syncthreads();

    // Hillis-Steele inclusive scan over thread totals
    for (int ofs = 1; ofs < SCAN_TPB; ofs <<= 1) {
        float x1 = (t >= ofs) ? sh1[t - ofs] : 0.0f;
        float x2 = (t >= ofs) ? sh2[t - ofs] : 0.0f;
        __syncthreads();
        sh1[t] += x1;
        sh2[t] += x2;
        __syncthreads();
    }

    if (active) {
        float off1 = (t > 0) ? sh1[t - 1] : 0.0f;
        float off2 = (t > 0) ? sh2[t - 1] : 0.0f;
        float w[SCAN_RPT];
#pragma unroll
        for (int k = 0; k < SCAN_RPT; k++) {
            float S1 = off1 + v1[k];
            float S2 = off2 + v2[k];
            w[k] = 1.0f / (1.0f + expf(S1 - S2));   // = w1 / (w1 + w2)
        }
        float4* pw = reinterpret_cast<float4*>(d_w1bar) + t * 2;
        pw[0] = make_float4(w[0], w[1], w[2], w[3]);
        pw[1] = make_float4(w[4], w[5], w[6], w[7]);
    }
}

// ---------------------------------------------------------------------------
// Kernel 2: out[i, j] = h[i] + g[i] * w1bar[j]   (256 MB of stores — the cost)
// Each thread owns one float4 of columns and loops over 16 rows.
// Streaming stores: output is write-once, never re-read.
// ---------------------------------------------------------------------------
__global__ void k_outer(float* __restrict__ out)
{
    int j4 = blockIdx.x * OUT_TPB + threadIdx.x;
    if (j4 >= N4) return;

    float4 w4 = reinterpret_cast<const float4*>(d_w1bar)[j4];
    int i0 = blockIdx.y * ROWS_PER_BLK;
    float4* o4 = reinterpret_cast<float4*>(out);

#pragma unroll
    for (int k = 0; k < ROWS_PER_BLK; k++) {
        int i = i0 + k;
        float gv = d_g[i];
        float hv = d_h[i];
        float4 o;
        o.x = fmaf(gv, w4.x, hv);
        o.y = fmaf(gv, w4.y, hv);
        o.z = fmaf(gv, w4.z, hv);
        o.w = fmaf(gv, w4.w, hv);
        __stcs(&o4[(size_t)i * N4 + j4], o);
    }
}

// ---------------------------------------------------------------------------
extern "C" void kernel_launch(void* const* d_in, const int* in_sizes, int n_in,
                              void* d_out, int out_size)
{
    const float* x   = (const float*)d_in[0];
    const float* a1  = (const float*)d_in[1];
    const float* c1  = (const float*)d_in[2];
    const float* a2  = (const float*)d_in[3];
    const float* c2  = (const float*)d_in[4];
    const float* wf1 = (const float*)d_in[5];
    const float* bf1 = (const float*)d_in[6];
    const float* wf2 = (const float*)d_in[7];
    const float* bf2 = (const float*)d_in[8];
    float* out = (float*)d_out;

    k_prologue<<<1, SCAN_TPB>>>(x, a1, c1, a2, c2, wf1, bf1, wf2, bf2);

    dim3 grid((N4 + OUT_TPB - 1) / OUT_TPB, N_ROWS / ROWS_PER_BLK);  // (8, 500)
    k_outer<<<grid, OUT_TPB>>>(out);
}